// round 9
// baseline (speedup 1.0000x reference)
#include <cuda_runtime.h>

// UWNeRF RGB renderer: R=65536 rays, S=128 samples.
// Warp-per-ray, 64-thread CTAs (32768 blocks): finer CTA granularity
// desynchronizes load/compute phases across the SM -> fewer DRAM idle gaps.
// __ldcg/__stcg: zero-reuse stream, bypass L1 allocation entirely.
// Compute body: 7 interleaved Kogge-Stone scans + telescoped object weights.
// Outputs: (rgb, restored, direct, backscatter), each [R,3], concatenated.

#define NUM_R 65536
#define NUM_S 128

__device__ __forceinline__ float clip01(float x) { return __saturatef(x); }

__global__ __launch_bounds__(64)
void uwnerf_render_kernel(
    const float* __restrict__ densities,     // [R,S,1]
    const float* __restrict__ rgbs,          // [R,S,3]
    const float* __restrict__ veiling,       // [R,S,3]
    const float* __restrict__ direct_coeffs, // [R,S,3]
    const float* __restrict__ backsc_coeffs, // [R,S,3]
    const float* __restrict__ deltas,        // [R,S,1]
    float* __restrict__ out)                 // [4, R, 3]
{
    const int r    = (blockIdx.x * blockDim.x + threadIdx.x) >> 5;
    const int lane = threadIdx.x & 31;

    const size_t sbase = (size_t)r * NUM_S;
    const size_t cbase = sbase * 3 + (size_t)lane * 12;

    // ---- loads: lane owns 4 contiguous samples -> coalesced LDG.E.128.CG ---
    const float4 dl = __ldcg(reinterpret_cast<const float4*>(deltas    + sbase) + lane);
    const float4 de = __ldcg(reinterpret_cast<const float4*>(densities + sbase) + lane);
    const float dlt[4] = {dl.x, dl.y, dl.z, dl.w};

    float rgbv[12], veilv[12];
    {
        const float4* p = reinterpret_cast<const float4*>(rgbs + cbase);
        *reinterpret_cast<float4*>(&rgbv[0]) = __ldcg(p + 0);
        *reinterpret_cast<float4*>(&rgbv[4]) = __ldcg(p + 1);
        *reinterpret_cast<float4*>(&rgbv[8]) = __ldcg(p + 2);
        p = reinterpret_cast<const float4*>(veiling + cbase);
        *reinterpret_cast<float4*>(&veilv[0]) = __ldcg(p + 0);
        *reinterpret_cast<float4*>(&veilv[4]) = __ldcg(p + 1);
        *reinterpret_cast<float4*>(&veilv[8]) = __ldcg(p + 2);
    }

    // ---- build local inclusive prefixes for 7 scan channels ----
    // ch 0: delta*density; ch 1-3: delta*direct[c]; ch 4-6: delta*backsc[c]
    float P[7][4];
    {
        P[0][0] = dlt[0] * de.x;
        P[0][1] = P[0][0] + dlt[1] * de.y;
        P[0][2] = P[0][1] + dlt[2] * de.z;
        P[0][3] = P[0][2] + dlt[3] * de.w;

        float dircv[12], bscv[12];
        const float4* p = reinterpret_cast<const float4*>(direct_coeffs + cbase);
        *reinterpret_cast<float4*>(&dircv[0]) = __ldcg(p + 0);
        *reinterpret_cast<float4*>(&dircv[4]) = __ldcg(p + 1);
        *reinterpret_cast<float4*>(&dircv[8]) = __ldcg(p + 2);
        p = reinterpret_cast<const float4*>(backsc_coeffs + cbase);
        *reinterpret_cast<float4*>(&bscv[0]) = __ldcg(p + 0);
        *reinterpret_cast<float4*>(&bscv[4]) = __ldcg(p + 1);
        *reinterpret_cast<float4*>(&bscv[8]) = __ldcg(p + 2);

        #pragma unroll
        for (int c = 0; c < 3; c++) {
            P[1 + c][0] = dlt[0] * dircv[0 * 3 + c];
            P[4 + c][0] = dlt[0] * bscv[0 * 3 + c];
            #pragma unroll
            for (int j = 1; j < 4; j++) {
                P[1 + c][j] = P[1 + c][j - 1] + dlt[j] * dircv[j * 3 + c];
                P[4 + c][j] = P[4 + c][j - 1] + dlt[j] * bscv[j * 3 + c];
            }
        }
    }

    // ---- 7 interleaved Kogge-Stone warp scans (independent shfl chains) ----
    float le[7];
    {
        float x[7];
        #pragma unroll
        for (int i = 0; i < 7; i++) x[i] = P[i][3];
        #pragma unroll
        for (int off = 1; off < 32; off <<= 1) {
            #pragma unroll
            for (int i = 0; i < 7; i++) {
                float y = __shfl_up_sync(0xffffffffu, x[i], off);
                x[i] += (lane >= off) ? y : 0.0f;
            }
        }
        #pragma unroll
        for (int i = 0; i < 7; i++) le[i] = x[i] - P[i][3];
    }

    // ---- object weights via telescoping: w_j = E_j - E_{j+1} ----
    float w[4];
    float wsum;
    float rest[3];
    {
        float E[5];
        E[0] = __expf(-le[0]);
        #pragma unroll
        for (int j = 0; j < 4; j++) E[j + 1] = __expf(-(le[0] + P[0][j]));
        #pragma unroll
        for (int j = 0; j < 4; j++) w[j] = E[j] - E[j + 1];
        wsum = E[0] - E[4];
        #pragma unroll
        for (int c = 0; c < 3; c++)
            rest[c] = w[0] * rgbv[c] + w[1] * rgbv[3 + c]
                    + w[2] * rgbv[6 + c] + w[3] * rgbv[9 + c];
    }

    // ---- direct & backscatter accumulation (24 independent exps) ----
    float dir[3], obs[3];
    #pragma unroll
    for (int c = 0; c < 3; c++) {
        const float ld = le[1 + c];
        float A0 = __expf(-ld);
        float A1 = __expf(-(ld + P[1 + c][0]));
        float A2 = __expf(-(ld + P[1 + c][1]));
        float A3 = __expf(-(ld + P[1 + c][2]));
        dir[c] = w[0] * A0 * rgbv[c]     + w[1] * A1 * rgbv[3 + c]
               + w[2] * A2 * rgbv[6 + c] + w[3] * A3 * rgbv[9 + c];

        const float lb = le[4 + c];
        float B0 = __expf(-lb);
        float B1 = __expf(-(lb + P[4 + c][0]));
        float B2 = __expf(-(lb + P[4 + c][1]));
        float B3 = __expf(-(lb + P[4 + c][2]));
        obs[c] = w[0] * (1.0f - B0) * veilv[c]
               + w[1] * (1.0f - B1) * veilv[3 + c]
               + w[2] * (1.0f - B2) * veilv[6 + c]
               + w[3] * (1.0f - B3) * veilv[9 + c];
    }

    // ---- warp reductions (10 accumulators, chains interleaved) ----
    #pragma unroll
    for (int off = 16; off > 0; off >>= 1) {
        wsum += __shfl_down_sync(0xffffffffu, wsum, off);
        #pragma unroll
        for (int c = 0; c < 3; c++) {
            rest[c] += __shfl_down_sync(0xffffffffu, rest[c], off);
            dir[c]  += __shfl_down_sync(0xffffffffu, dir[c], off);
            obs[c]  += __shfl_down_sync(0xffffffffu, obs[c], off);
        }
    }

    // ---- lane 0 owns sample 0 (veiling_light[:,0,:]) and writes outputs ----
    if (lane == 0) {
        const float omask = clip01(wsum);
        const size_t RT3 = (size_t)NUM_R * 3;
        #pragma unroll
        for (int c = 0; c < 3; c++) {
            float medium = (1.0f - omask) * veilv[c];  // veiling at s=0
            float bs_ray = obs[c] + medium;
            __stcg(out + 0 * RT3 + (size_t)r * 3 + c, clip01(dir[c] + bs_ray));
            __stcg(out + 1 * RT3 + (size_t)r * 3 + c, clip01(rest[c]));
            __stcg(out + 2 * RT3 + (size_t)r * 3 + c, clip01(dir[c]));
            __stcg(out + 3 * RT3 + (size_t)r * 3 + c, clip01(bs_ray));
        }
    }
}

extern "C" void kernel_launch(void* const* d_in, const int* in_sizes, int n_in,
                              void* d_out, int out_size) {
    const float* densities     = (const float*)d_in[0];
    const float* rgbs          = (const float*)d_in[1];
    const float* veiling       = (const float*)d_in[2];
    const float* direct_coeffs = (const float*)d_in[3];
    const float* backsc_coeffs = (const float*)d_in[4];
    const float* deltas        = (const float*)d_in[5];
    float* out = (float*)d_out;

    // 2 warps (2 rays) per 64-thread block -> 32768 blocks, exact cover.
    const int threads = 64;
    const int blocks  = (NUM_R * 32) / threads;
    uwnerf_render_kernel<<<blocks, threads>>>(
        densities, rgbs, veiling, direct_coeffs, backsc_coeffs, deltas, out);
}

// round 12
// speedup vs baseline: 1.0288x; 1.0288x over previous
#include <cuda_runtime.h>

// UWNeRF RGB renderer: R=65536 rays, S=128 samples.
// FINAL: best-measured variant (72.19us, DRAM ~83%). Seven structural
// variants (MLP pinning, cp.async pipelines, persistence, scan interleave,
// cache hints, block sizes) all converge at 6.55-6.66 TB/s with minimal
// traffic (469.8MB read, every byte touched once) -> effective HBM read
// ceiling for this mix. Warp-per-ray, lane l owns contiguous samples
// [4l,4l+3] -> every load is a coalesced float4 LDG.E.128.
// Outputs: (rgb, restored, direct, backscatter), each [R,3], concatenated.

#define NUM_R 65536
#define NUM_S 128

__device__ __forceinline__ float clip01(float x) { return __saturatef(x); }

// Pinned 128-bit global load: volatile asm -> not reordered in PTX.
__device__ __forceinline__ void ldg128(const float* p, float* d) {
    asm volatile("ld.global.v4.f32 {%0,%1,%2,%3}, [%4];"
                 : "=f"(d[0]), "=f"(d[1]), "=f"(d[2]), "=f"(d[3])
                 : "l"(p));
}

// Exclusive prefix sum over 128 samples distributed 4-per-lane (contiguous).
__device__ __forceinline__ void warp_excl_scan4(const float v[4], float excl[4], int lane) {
    float p0 = v[0];
    float p1 = p0 + v[1];
    float p2 = p1 + v[2];
    float p3 = p2 + v[3];
    float x = p3;
    #pragma unroll
    for (int off = 1; off < 32; off <<= 1) {
        float y = __shfl_up_sync(0xffffffffu, x, off);
        x += (lane >= off) ? y : 0.0f;
    }
    float le = x - p3;  // exclusive prefix of this lane's 4-sample block
    excl[0] = le;
    excl[1] = le + p0;
    excl[2] = le + p1;
    excl[3] = le + p2;
}

__global__ __launch_bounds__(128)
void uwnerf_render_kernel(
    const float* __restrict__ densities,     // [R,S,1]
    const float* __restrict__ rgbs,          // [R,S,3]
    const float* __restrict__ veiling,       // [R,S,3]
    const float* __restrict__ direct_coeffs, // [R,S,3]
    const float* __restrict__ backsc_coeffs, // [R,S,3]
    const float* __restrict__ deltas,        // [R,S,1]
    float* __restrict__ out)                 // [4, R, 3]
{
    // Grid exactly covers NUM_R rays: no early exit (full-warp shfls).
    const int r    = (blockIdx.x * blockDim.x + threadIdx.x) >> 5;
    const int lane = threadIdx.x & 31;

    const size_t sbase = (size_t)r * NUM_S + (size_t)lane * 4;       // scalar
    const size_t cbase = (size_t)r * NUM_S * 3 + (size_t)lane * 12;  // 3-chan

    // ============ FRONT-LOADED MEMORY PHASE: 14 x LDG.E.128 =================
    float dlv[4], dev[4];
    float rgbv[12], veilv[12], dircv[12], bscv[12];
    ldg128(deltas    + sbase, dlv);
    ldg128(densities + sbase, dev);
    ldg128(rgbs + cbase + 0, &rgbv[0]);
    ldg128(rgbs + cbase + 4, &rgbv[4]);
    ldg128(rgbs + cbase + 8, &rgbv[8]);
    ldg128(veiling + cbase + 0, &veilv[0]);
    ldg128(veiling + cbase + 4, &veilv[4]);
    ldg128(veiling + cbase + 8, &veilv[8]);
    ldg128(direct_coeffs + cbase + 0, &dircv[0]);
    ldg128(direct_coeffs + cbase + 4, &dircv[4]);
    ldg128(direct_coeffs + cbase + 8, &dircv[8]);
    ldg128(backsc_coeffs + cbase + 0, &bscv[0]);
    ldg128(backsc_coeffs + cbase + 4, &bscv[4]);
    ldg128(backsc_coeffs + cbase + 8, &bscv[8]);

    float dd[4];
    #pragma unroll
    for (int j = 0; j < 4; j++) dd[j] = dlv[j] * dev[j];

    // ================= COMPUTE PHASE ========================================
    // ---- object transmittance / weights ----
    float ex[4];
    warp_excl_scan4(dd, ex, lane);

    float w[4];
    float wsum = 0.0f;
    float rest[3] = {0.0f, 0.0f, 0.0f};
    #pragma unroll
    for (int j = 0; j < 4; j++) {
        float T     = __expf(-ex[j]);
        float alpha = 1.0f - __expf(-dd[j]);
        w[j] = alpha * T;
        wsum += w[j];
        rest[0] += w[j] * rgbv[j * 3 + 0];
        rest[1] += w[j] * rgbv[j * 3 + 1];
        rest[2] += w[j] * rgbv[j * 3 + 2];
    }

    // ---- direct attenuation: 3 scans over delta*direct_coeffs ----
    float dir[3] = {0.0f, 0.0f, 0.0f};
    #pragma unroll
    for (int c = 0; c < 3; c++) {
        float v[4], e[4];
        #pragma unroll
        for (int j = 0; j < 4; j++) v[j] = dlv[j] * dircv[j * 3 + c];
        warp_excl_scan4(v, e, lane);
        #pragma unroll
        for (int j = 0; j < 4; j++)
            dir[c] += w[j] * __expf(-e[j]) * rgbv[j * 3 + c];
    }

    // ---- backscatter attenuation: 3 scans over delta*backscatter_coeffs ----
    float obs[3] = {0.0f, 0.0f, 0.0f};
    #pragma unroll
    for (int c = 0; c < 3; c++) {
        float v[4], e[4];
        #pragma unroll
        for (int j = 0; j < 4; j++) v[j] = dlv[j] * bscv[j * 3 + c];
        warp_excl_scan4(v, e, lane);
        #pragma unroll
        for (int j = 0; j < 4; j++)
            obs[c] += w[j] * (1.0f - __expf(-e[j])) * veilv[j * 3 + c];
    }

    // ---- warp reductions (10 accumulators) ----
    #pragma unroll
    for (int off = 16; off > 0; off >>= 1) {
        wsum += __shfl_down_sync(0xffffffffu, wsum, off);
        #pragma unroll
        for (int c = 0; c < 3; c++) {
            rest[c] += __shfl_down_sync(0xffffffffu, rest[c], off);
            dir[c]  += __shfl_down_sync(0xffffffffu, dir[c], off);
            obs[c]  += __shfl_down_sync(0xffffffffu, obs[c], off);
        }
    }

    // ---- lane 0 owns sample 0 (veiling_light[:,0,:]) and writes outputs ----
    if (lane == 0) {
        const float omask = clip01(wsum);
        const size_t RT3 = (size_t)NUM_R * 3;
        #pragma unroll
        for (int c = 0; c < 3; c++) {
            float medium = (1.0f - omask) * veilv[c];  // veiling at s=0
            float bs_ray = obs[c] + medium;
            out[0 * RT3 + (size_t)r * 3 + c] = clip01(dir[c] + bs_ray);  // rgb
            out[1 * RT3 + (size_t)r * 3 + c] = clip01(rest[c]);          // restored
            out[2 * RT3 + (size_t)r * 3 + c] = clip01(dir[c]);           // direct
            out[3 * RT3 + (size_t)r * 3 + c] = clip01(bs_ray);           // backscatter
        }
    }
}

extern "C" void kernel_launch(void* const* d_in, const int* in_sizes, int n_in,
                              void* d_out, int out_size) {
    const float* densities     = (const float*)d_in[0];
    const float* rgbs          = (const float*)d_in[1];
    const float* veiling       = (const float*)d_in[2];
    const float* direct_coeffs = (const float*)d_in[3];
    const float* backsc_coeffs = (const float*)d_in[4];
    const float* deltas        = (const float*)d_in[5];
    float* out = (float*)d_out;

    // 4 warps (4 rays) per 128-thread block -> 16384 blocks, exact cover.
    const int threads = 128;
    const int blocks  = (NUM_R * 32) / threads;
    uwnerf_render_kernel<<<blocks, threads>>>(
        densities, rgbs, veiling, direct_coeffs, backsc_coeffs, deltas, out);
}